// round 5
// baseline (speedup 1.0000x reference)
#include <cuda_runtime.h>
#include <cuda_bf16.h>
#include <cstdint>

#define NPL   16384
#define DEG   16
#define DIM   128
#define L_LEV 8
#define NT    256

// byte strides (row pitch) — 16B pad keeps ldmatrix rows 4 banks apart
#define STR_A 272    // 128 bf16 + 16B pad
#define STR_B 144    // 64  bf16 + 16B pad

// per-MLP weight blob offsets (bytes): [N][K] bf16, padded stride; hi then lo contiguous
#define WL1H 0
#define WL1L 17408          // 64 * 272
#define WL2H 34816
#define WL2L 44032          // +64*144
#define WL3H 53248
#define WL3L 71680          // +128*144
#define WBLOB 90112

// smem layout (bytes)
#define OFF_W0   0            // slot0: W1 (hi 17408 + lo 17408) or W3 (hi 18432 + lo 18432)
#define OFF_W1S  36864        // slot1: W2 (hi 9216 + lo 9216)
#define OFF_AH   55296        // activation A hi [64][STR_A]
#define OFF_AL   72704
#define OFF_BH   90112        // activation B hi [64][STR_B]
#define OFF_BL   99328
#define OFF_IDX  90112        // gather indices (8 KB), aliases B buffers
#define OFF_BIAS 108544       // 512 floats
#define SM_TOTAL 110592       // -> 2 CTAs/SM

__device__ __align__(16) float   g_inv[7 * NPL * DIM];   // inv-MLP outputs per node
__device__ __align__(16) uint8_t g_wb[2 * WBLOB];        // bf16 hi/lo weights (and, inv)

__device__ __forceinline__ float leaky(float v) { return v >= 0.f ? v : 0.01f * v; }

// pack two f32 -> bf16x2 (hi reconstruct via shifts), lo = residual pair
__device__ __forceinline__ void split2(float f0, float f1, uint32_t& hi, uint32_t& lo) {
    asm("cvt.rn.bf16x2.f32 %0, %1, %2;" : "=r"(hi) : "f"(f1), "f"(f0));
    float hf0 = __uint_as_float(hi << 16);
    float hf1 = __uint_as_float(hi & 0xFFFF0000u);
    float r0 = f0 - hf0, r1 = f1 - hf1;
    asm("cvt.rn.bf16x2.f32 %0, %1, %2;" : "=r"(lo) : "f"(r1), "f"(r0));
}

__device__ __forceinline__ uint32_t smem_u32(const void* p) {
    uint32_t a;
    asm("{ .reg .u64 t; cvta.to.shared.u64 t, %1; cvt.u32.u64 %0, t; }" : "=r"(a) : "l"(p));
    return a;
}
__device__ __forceinline__ void ldm4(uint32_t addr, uint32_t r[4]) {
    asm volatile("ldmatrix.sync.aligned.m8n8.x4.shared.b16 {%0,%1,%2,%3}, [%4];"
                 : "=r"(r[0]), "=r"(r[1]), "=r"(r[2]), "=r"(r[3]) : "r"(addr));
}
__device__ __forceinline__ void mma16816(float c[4], const uint32_t a[4],
                                         uint32_t b0, uint32_t b1) {
    asm volatile("mma.sync.aligned.m16n8k16.row.col.f32.bf16.bf16.f32 "
                 "{%0,%1,%2,%3}, {%4,%5,%6,%7}, {%8,%9}, {%0,%1,%2,%3};"
                 : "+f"(c[0]), "+f"(c[1]), "+f"(c[2]), "+f"(c[3])
                 : "r"(a[0]), "r"(a[1]), "r"(a[2]), "r"(a[3]), "r"(b0), "r"(b1));
}

// ---------------- weight prep: fp32 [K][N] -> bf16 hi/lo [N][K] padded ----------------
__global__ void prep_weights(const float* aw1, const float* aw2, const float* aw3,
                             const float* iw1, const float* iw2, const float* iw3)
{
    const int b = blockIdx.x;          // 0..2 and, 3..5 inv
    const int layer = b % 3;
    const uint32_t base = (b < 3) ? 0u : (uint32_t)WBLOB;
    const float* W; int K, N; uint32_t stride, offH, offL;
    if (layer == 0)      { K = 128; N = 64;  stride = STR_A; offH = WL1H; offL = WL1L; W = (b < 3) ? aw1 : iw1; }
    else if (layer == 1) { K = 64;  N = 64;  stride = STR_B; offH = WL2H; offL = WL2L; W = (b < 3) ? aw2 : iw2; }
    else                 { K = 64;  N = 128; stride = STR_B; offH = WL3H; offL = WL3L; W = (b < 3) ? aw3 : iw3; }
    uint8_t* oH = g_wb + base + offH;
    uint8_t* oL = g_wb + base + offL;
    const int slots = N * (int)(stride / 2);
    for (int idx = threadIdx.x; idx < slots; idx += blockDim.x) {
        int n = idx / (stride / 2);
        int s = idx % (stride / 2);
        __nv_bfloat16 hv = __float2bfloat16(0.f), lv = __float2bfloat16(0.f);
        if (s < K) {
            float f = W[s * N + n];
            hv = __float2bfloat16(f);
            lv = __float2bfloat16(f - __bfloat162float(hv));
        }
        *(__nv_bfloat16*)(oH + (size_t)n * stride + (size_t)s * 2) = hv;
        *(__nv_bfloat16*)(oL + (size_t)n * stride + (size_t)s * 2) = lv;
    }
}

__device__ __forceinline__ void stage_bytes(uint8_t* dst, const uint8_t* g, int bytes, int tid) {
    const uint4* s4 = (const uint4*)g;
    uint4* d4 = (uint4*)dst;
    for (int i = tid; i < bytes / 16; i += NT) d4[i] = s4[i];
}

// ---------------- warp-tile GEMM: C[16 x NB8*8] += (Ah+Al)@(Bh+Bl)^T ----------------
template <int KSTEPS, int NB8>
__device__ __forceinline__ void mma_layer(uint32_t aHi, uint32_t aLo, uint32_t strideA,
                                          uint32_t wHi, uint32_t wLo, uint32_t strideB,
                                          int mt, int n0, int lane, float acc[][4])
{
#pragma unroll
    for (int i = 0; i < NB8; i++) { acc[i][0] = acc[i][1] = acc[i][2] = acc[i][3] = 0.f; }
    const uint32_t aRow = (uint32_t)(mt * 16 + (lane & 15)) * strideA + (uint32_t)(lane >> 4) * 16u;
#pragma unroll
    for (int kb = 0; kb < KSTEPS; kb++) {
        uint32_t ah[4], al[4];
        ldm4(aHi + aRow + (uint32_t)kb * 32u, ah);
        ldm4(aLo + aRow + (uint32_t)kb * 32u, al);
#pragma unroll
        for (int s = 0; s < NB8 / 4; s++) {
            const uint32_t bRow = (uint32_t)(n0 + s * 32 + lane) * strideB + (uint32_t)kb * 32u;
            uint32_t bh0[4], bh1[4], bl0[4], bl1[4];
            ldm4(wHi + bRow, bh0);
            ldm4(wHi + bRow + 16u, bh1);
            ldm4(wLo + bRow, bl0);
            ldm4(wLo + bRow + 16u, bl1);
#pragma unroll
            for (int nf = 0; nf < 4; nf++) {
                mma16816(acc[s * 4 + nf], ah, bh0[nf], bh1[nf]);
                mma16816(acc[s * 4 + nf], ah, bl0[nf], bl1[nf]);
                mma16816(acc[s * 4 + nf], al, bh0[nf], bh1[nf]);
            }
        }
    }
}

// ---------------- mid-layer epilogue: bias + leaky + split -> smem hi/lo ----------------
template <int NB8>
__device__ __forceinline__ void epi_mid(const float acc[][4], const float* bias,
                                        uint8_t* smem, uint32_t outHi, uint32_t outLo,
                                        uint32_t strideOut, int mt, int n0, int lane)
{
    const int qr = lane >> 2, qc = (lane & 3) * 2;
#pragma unroll
    for (int nf = 0; nf < NB8; nf++) {
        const int col = n0 + nf * 8 + qc;
        const float b0 = bias[col], b1 = bias[col + 1];
#pragma unroll
        for (int hf = 0; hf < 2; hf++) {
            const int row = mt * 16 + qr + hf * 8;
            float f0 = leaky(acc[nf][hf * 2 + 0] + b0);
            float f1 = leaky(acc[nf][hf * 2 + 1] + b1);
            uint32_t hi, lo; split2(f0, f1, hi, lo);
            *(uint32_t*)(smem + outHi + (size_t)row * strideOut + (size_t)col * 2) = hi;
            *(uint32_t*)(smem + outLo + (size_t)row * strideOut + (size_t)col * 2) = lo;
        }
    }
}

// ---------------- final epilogue: bias -> gmem fp32 (+ optional chain into A) ----------
template <int CHAIN>
__device__ __forceinline__ void epi_final(const float acc[][4], const float* bias,
                                          float* __restrict__ gout, uint8_t* smem,
                                          int mt, int n0, int lane)
{
    const int qr = lane >> 2, qc = (lane & 3) * 2;
    float vv[8][4];
#pragma unroll
    for (int nf = 0; nf < 8; nf++) {
        const int col = n0 + nf * 8 + qc;
        const float b0 = bias[col], b1 = bias[col + 1];
#pragma unroll
        for (int hf = 0; hf < 2; hf++) {
            vv[nf][hf * 2 + 0] = acc[nf][hf * 2 + 0] + b0;
            vv[nf][hf * 2 + 1] = acc[nf][hf * 2 + 1] + b1;
            const int row = mt * 16 + qr + hf * 8;
            *(float2*)&gout[(size_t)row * DIM + col] =
                make_float2(vv[nf][hf * 2 + 0], vv[nf][hf * 2 + 1]);
        }
    }
    if (CHAIN) {
        __syncthreads();   // all warps done with mma3 reads before A overwrite
#pragma unroll
        for (int nf = 0; nf < 8; nf++) {
            const int col = n0 + nf * 8 + qc;
#pragma unroll
            for (int hf = 0; hf < 2; hf++) {
                const int row = mt * 16 + qr + hf * 8;
                uint32_t hi, lo; split2(vv[nf][hf * 2 + 0], vv[nf][hf * 2 + 1], hi, lo);
                *(uint32_t*)(smem + OFF_AH + (size_t)row * STR_A + (size_t)col * 2) = hi;
                *(uint32_t*)(smem + OFF_AL + (size_t)row * STR_A + (size_t)col * 2) = lo;
            }
        }
    }
}

// ---------------- one full 3-layer MLP (A[64][128] in smem, W1 pre-staged) ----------------
// Caller must have staged W1 into slot0 and synced.
template <int CHAIN>
__device__ __forceinline__ void run_mlp(uint8_t* smem, uint32_t SB, const uint8_t* wb,
                                        const float* bias, float* __restrict__ gout, int tid)
{
    const int lane = tid & 31, w = tid >> 5;
    const int mt = w & 3, nh = w >> 2;
    float acc[8][4];

    // Prefetch W2 into slot1 (no reader until after next sync)
    stage_bytes(smem + OFF_W1S, wb + WL2H, 18432, tid);

    // L1: [64,128] @ W1[128->64]
    mma_layer<8, 4>(SB + OFF_AH, SB + OFF_AL, STR_A,
                    SB + OFF_W0, SB + OFF_W0 + 17408, STR_A, mt, nh * 32, lane, acc);
    epi_mid<4>(acc, bias, smem, OFF_BH, OFF_BL, STR_B, mt, nh * 32, lane);
    __syncthreads();     // B ready, W2 visible, W1/slot0 free

    // Prefetch W3 into slot0 (overlaps L2 MMA)
    stage_bytes(smem + OFF_W0, wb + WL3H, 36864, tid);

    // L2: [64,64] @ W2[64->64]
    mma_layer<4, 4>(SB + OFF_BH, SB + OFF_BL, STR_B,
                    SB + OFF_W1S, SB + OFF_W1S + 9216, STR_B, mt, nh * 32, lane, acc);
    epi_mid<4>(acc, bias + 64, smem, OFF_AH, OFF_AL, STR_A, mt, nh * 32, lane);
    __syncthreads();     // A2 ready, W3 visible

    // L3: [64,64] @ W3[64->128]
    mma_layer<4, 8>(SB + OFF_AH, SB + OFF_AL, STR_A,
                    SB + OFF_W0, SB + OFF_W0 + 18432, STR_B, mt, nh * 64, lane, acc);
    epi_final<CHAIN>(acc, bias + 128, gout, smem, mt, nh * 64, lane);
}

// ---------------- fused per-level kernel ----------------
// mode 0: inv-MLP on hin rows (level-0 sources). mode 1: gather -> and-MLP -> (inv-MLP)
__global__ __launch_bounds__(NT, 2)
void fused_kernel(const float* __restrict__ hin, float* __restrict__ h,
                  const int* __restrict__ src, const int* __restrict__ mask,
                  const float* ab1, const float* ab2, const float* ab3,
                  const float* ib1, const float* ib2, const float* ib3,
                  int lvl, int mode, int do_inv)
{
    extern __shared__ __align__(16) uint8_t smem[];
    const uint32_t SB = smem_u32(smem);
    const int tid = threadIdx.x;
    const int lane = tid & 31, w = tid >> 5;
    float* ginv = g_inv;
    float* BIAS = (float*)(smem + OFF_BIAS);

    if (tid < 64) {
        BIAS[tid] = ab1[tid];       BIAS[64 + tid] = ab2[tid];
        BIAS[256 + tid] = ib1[tid]; BIAS[320 + tid] = ib2[tid];
    }
    if (tid < 128) { BIAS[128 + tid] = ab3[tid]; BIAS[384 + tid] = ib3[tid]; }

    const int nodebase = blockIdx.x * 64;

    if (mode == 0) {
        // stage inv-W1 while building A from hin
        stage_bytes(smem + OFF_W0, g_wb + WBLOB + WL1H, 34816, tid);
        const float4* in4 = (const float4*)(hin + (size_t)nodebase * DIM);
        for (int i = tid; i < 64 * 32; i += NT) {
            const int row = i >> 5, c4 = i & 31;
            float4 x = in4[(size_t)row * 32 + c4];
            uint32_t h0, l0, h1, l1;
            split2(x.x, x.y, h0, l0);
            split2(x.z, x.w, h1, l1);
            const size_t off = (size_t)row * STR_A + (size_t)c4 * 8;
            *(uint32_t*)(smem + OFF_AH + off) = h0;
            *(uint32_t*)(smem + OFF_AH + off + 4) = h1;
            *(uint32_t*)(smem + OFF_AL + off) = l0;
            *(uint32_t*)(smem + OFF_AL + off + 4) = l1;
        }
        __syncthreads();
        float* gout = ginv + (size_t)nodebase * DIM;
        run_mlp<0>(smem, SB, g_wb + WBLOB, BIAS + 256, gout, tid);
        return;
    }

    // ---- mode 1: stage and-W1 + indices, then gather ----
    stage_bytes(smem + OFF_W0, g_wb + WL1H, 34816, tid);
    {
        int4* idx4 = (int4*)(smem + OFF_IDX);
        idx4[tid]       = ((const int4*)(src  + (size_t)nodebase * DEG))[tid];
        idx4[256 + tid] = ((const int4*)(mask + (size_t)nodebase * DEG))[tid];
    }
    __syncthreads();
    {
        const int* sidx = (const int*)(smem + OFF_IDX);
        const int* midx = sidx + 1024;
        for (int rr = 0; rr < 8; rr += 2) {
            const int r0 = w * 8 + rr, r1 = r0 + 1;
            float4 a0 = make_float4(0.f, 0.f, 0.f, 0.f);
            float4 a1 = make_float4(0.f, 0.f, 0.f, 0.f);
#pragma unroll 8
            for (int e = 0; e < DEG; e++) {
                const int s0 = sidx[r0 * DEG + e], m0 = midx[r0 * DEG + e];
                const int s1 = sidx[r1 * DEG + e], m1 = midx[r1 * DEG + e];
                const float4* p0 = (const float4*)((m0 ? ginv : h) + (size_t)s0 * DIM);
                const float4* p1 = (const float4*)((m1 ? ginv : h) + (size_t)s1 * DIM);
                float4 v0 = p0[lane], v1 = p1[lane];
                a0.x += v0.x; a0.y += v0.y; a0.z += v0.z; a0.w += v0.w;
                a1.x += v1.x; a1.y += v1.y; a1.z += v1.z; a1.w += v1.w;
            }
            const float s16 = 0.0625f;
            uint32_t h0, l0, h1, l1;
            split2(a0.x * s16, a0.y * s16, h0, l0);
            split2(a0.z * s16, a0.w * s16, h1, l1);
            size_t off = (size_t)r0 * STR_A + (size_t)lane * 8;
            *(uint32_t*)(smem + OFF_AH + off) = h0;
            *(uint32_t*)(smem + OFF_AH + off + 4) = h1;
            *(uint32_t*)(smem + OFF_AL + off) = l0;
            *(uint32_t*)(smem + OFF_AL + off + 4) = l1;
            split2(a1.x * s16, a1.y * s16, h0, l0);
            split2(a1.z * s16, a1.w * s16, h1, l1);
            off = (size_t)r1 * STR_A + (size_t)lane * 8;
            *(uint32_t*)(smem + OFF_AH + off) = h0;
            *(uint32_t*)(smem + OFF_AH + off + 4) = h1;
            *(uint32_t*)(smem + OFF_AL + off) = l0;
            *(uint32_t*)(smem + OFF_AL + off + 4) = l1;
        }
    }
    __syncthreads();

    float* gout = h + ((size_t)(lvl + 1) * NPL + (size_t)nodebase) * DIM;
    if (do_inv) {
        run_mlp<1>(smem, SB, g_wb, BIAS, gout, tid);
        // chain: A now holds and-output; stage inv-W1 and go again
        stage_bytes(smem + OFF_W0, g_wb + WBLOB + WL1H, 34816, tid);
        __syncthreads();
        float* gi = ginv + ((size_t)(lvl + 1) * NPL + (size_t)nodebase) * DIM;
        run_mlp<0>(smem, SB, g_wb + WBLOB, BIAS + 256, gi, tid);
    } else {
        run_mlp<0>(smem, SB, g_wb, BIAS, gout, tid);
    }
}

// ---------------------------------------------------------------------------
extern "C" void kernel_launch(void* const* d_in, const int* in_sizes, int n_in,
                              void* d_out, int out_size)
{
    (void)in_sizes; (void)n_in; (void)out_size;
    const float* h_in  = (const float*)d_in[0];
    const int*   esrc  = (const int*)d_in[1];
    const int*   emask = (const int*)d_in[2];
    const float* iw1 = (const float*)d_in[3];
    const float* ib1 = (const float*)d_in[4];
    const float* iw2 = (const float*)d_in[5];
    const float* ib2 = (const float*)d_in[6];
    const float* iw3 = (const float*)d_in[7];
    const float* ib3 = (const float*)d_in[8];
    const float* aw1 = (const float*)d_in[9];
    const float* ab1 = (const float*)d_in[10];
    const float* aw2 = (const float*)d_in[11];
    const float* ab2 = (const float*)d_in[12];
    const float* aw3 = (const float*)d_in[13];
    const float* ab3 = (const float*)d_in[14];

    float* h = (float*)d_out;

    static bool once = false;
    if (!once) {
        cudaFuncSetAttribute(fused_kernel, cudaFuncAttributeMaxDynamicSharedMemorySize, SM_TOTAL);
        once = true;
    }

    // level-0 rows of the output are the input rows
    cudaMemcpyAsync(h, h_in, (size_t)NPL * DIM * sizeof(float), cudaMemcpyDeviceToDevice, 0);

    prep_weights<<<6, 256>>>(aw1, aw2, aw3, iw1, iw2, iw3);

    const int grid = NPL / 64;   // 256 CTAs

    // inv features of level-0 sources
    fused_kernel<<<grid, NT, SM_TOTAL>>>(h_in, h, esrc, emask,
                                         ab1, ab2, ab3, ib1, ib2, ib3, 0, 0, 0);

    for (int lvl = 0; lvl < L_LEV - 1; lvl++) {
        const int* s = esrc  + (size_t)lvl * NPL * DEG;
        const int* m = emask + (size_t)lvl * NPL * DEG;
        fused_kernel<<<grid, NT, SM_TOTAL>>>(h_in, h, s, m,
                                             ab1, ab2, ab3, ib1, ib2, ib3,
                                             lvl, 1, (lvl < L_LEV - 2) ? 1 : 0);
    }
}

// round 6
// speedup vs baseline: 1.1033x; 1.1033x over previous
#include <cuda_runtime.h>
#include <cuda_bf16.h>
#include <cstdint>

#define NPL    16384
#define DEG    16
#define DIM    128
#define NT     512
#define GRIDSZ 148
#define NTILES 256    // 64-row tiles per level

// activation byte strides (16B pad -> conflict-free ldmatrix)
#define STR_A 272
#define STR_B 144

// swizzled weight blob offsets (per MLP, bytes). [N][K] bf16, no pad, XOR-16B swizzle
#define WL1H 0
#define WL1L 16384      // 64 x 256B
#define WL2H 32768
#define WL2L 40960      // 64 x 128B
#define WL3H 49152
#define WL3L 65536      // 128 x 128B
#define WBLOB 81920

// smem layout (bytes)
#define OFF_W    0            // both blobs resident: 163840
#define OFF_AH   163840       // A hi [64][STR_A] = 17408
#define OFF_AL   181248
#define OFF_BH   198656       // B hi [64][STR_B] = 9216
#define OFF_BL   207872
#define OFF_IDX  198656       // gather indices (8 KB), aliases B
#define OFF_BIAS 217088       // 512 floats
#define SM_TOTAL 219136       // 214 KB -> 1 CTA/SM

__device__ __align__(16) float   g_inv[7 * NPL * DIM];
__device__ __align__(16) uint8_t g_wb[2 * WBLOB];
__device__ unsigned g_bar;

__device__ __forceinline__ float leaky(float v) { return v >= 0.f ? v : 0.01f * v; }

__device__ __forceinline__ void split2(float f0, float f1, uint32_t& hi, uint32_t& lo) {
    asm("cvt.rn.bf16x2.f32 %0, %1, %2;" : "=r"(hi) : "f"(f1), "f"(f0));
    float hf0 = __uint_as_float(hi << 16);
    float hf1 = __uint_as_float(hi & 0xFFFF0000u);
    float r0 = f0 - hf0, r1 = f1 - hf1;
    asm("cvt.rn.bf16x2.f32 %0, %1, %2;" : "=r"(lo) : "f"(r1), "f"(r0));
}

__device__ __forceinline__ uint32_t smem_u32(const void* p) {
    uint32_t a;
    asm("{ .reg .u64 t; cvta.to.shared.u64 t, %1; cvt.u32.u64 %0, t; }" : "=r"(a) : "l"(p));
    return a;
}
__device__ __forceinline__ void ldm4(uint32_t addr, uint32_t r[4]) {
    asm volatile("ldmatrix.sync.aligned.m8n8.x4.shared.b16 {%0,%1,%2,%3}, [%4];"
                 : "=r"(r[0]), "=r"(r[1]), "=r"(r[2]), "=r"(r[3]) : "r"(addr));
}
__device__ __forceinline__ void mma16816(float c[4], const uint32_t a[4],
                                         uint32_t b0, uint32_t b1) {
    asm volatile("mma.sync.aligned.m16n8k16.row.col.f32.bf16.bf16.f32 "
                 "{%0,%1,%2,%3}, {%4,%5,%6,%7}, {%8,%9}, {%0,%1,%2,%3};"
                 : "+f"(c[0]), "+f"(c[1]), "+f"(c[2]), "+f"(c[3])
                 : "r"(a[0]), "r"(a[1]), "r"(a[2]), "r"(a[3]), "r"(b0), "r"(b1));
}

// ---------------- grid barrier (all GRIDSZ CTAs resident) ----------------
__device__ __forceinline__ void grid_barrier(unsigned target) {
    __syncthreads();
    if (threadIdx.x == 0) {
        asm volatile("red.release.gpu.add.u32 [%0], 1;" :: "l"(&g_bar) : "memory");
        unsigned v;
        do {
            asm volatile("ld.acquire.gpu.u32 %0, [%1];" : "=r"(v) : "l"(&g_bar) : "memory");
        } while (v < target);
    }
    __syncthreads();
}

// ---------------- weight prep: fp32 [K][N] -> bf16 hi/lo [N][K] swizzled ----------------
__global__ void prep_weights(const float* aw1, const float* aw2, const float* aw3,
                             const float* iw1, const float* iw2, const float* iw3)
{
    if (blockIdx.x == 0 && threadIdx.x == 0) g_bar = 0;   // reset barrier per launch
    const int b = blockIdx.x;          // 0..2 and, 3..5 inv
    const int layer = b % 3;
    const uint32_t base = (b < 3) ? 0u : (uint32_t)WBLOB;
    const float* W; int K, N; uint32_t offH, offL;
    if (layer == 0)      { K = 128; N = 64;  offH = WL1H; offL = WL1L; W = (b < 3) ? aw1 : iw1; }
    else if (layer == 1) { K = 64;  N = 64;  offH = WL2H; offL = WL2L; W = (b < 3) ? aw2 : iw2; }
    else                 { K = 64;  N = 128; offH = WL3H; offL = WL3L; W = (b < 3) ? aw3 : iw3; }
    uint8_t* oH = g_wb + base + offH;
    uint8_t* oL = g_wb + base + offL;
    const uint32_t stride = (uint32_t)K * 2u;
    for (int idx = threadIdx.x; idx < N * K; idx += blockDim.x) {
        const int n = idx / K, k = idx % K;
        float f = W[k * N + n];
        __nv_bfloat16 hv = __float2bfloat16(f);
        __nv_bfloat16 lv = __float2bfloat16(f - __bfloat162float(hv));
        const uint32_t byte = (uint32_t)n * stride +
                              ((((uint32_t)(k >> 3) ^ (uint32_t)(n & 7)) << 4)) +
                              (uint32_t)(k & 7) * 2u;
        *(__nv_bfloat16*)(oH + byte) = hv;
        *(__nv_bfloat16*)(oL + byte) = lv;
    }
}

// ---------------- warp-tile GEMM with swizzled weights ----------------
// B side: one ldm4 per 16 n-rows loads both k-chunks of a k16 step.
template <int KSTEPS, int NB8>
__device__ __forceinline__ void mma_layer(uint32_t aHi, uint32_t aLo, uint32_t strideA,
                                          uint32_t wHi, uint32_t wLo, uint32_t strideW,
                                          int mt, int n0, int lane, float acc[][4])
{
#pragma unroll
    for (int i = 0; i < NB8; i++) { acc[i][0] = acc[i][1] = acc[i][2] = acc[i][3] = 0.f; }
    const uint32_t aRow = (uint32_t)(mt * 16 + (lane & 15)) * strideA + (uint32_t)(lane >> 4) * 16u;
    const int brow = lane & 15;
    const uint32_t bsel = (uint32_t)(lane >> 4);
#pragma unroll
    for (int kb = 0; kb < KSTEPS; kb++) {
        uint32_t ah[4], al[4];
        ldm4(aHi + aRow + (uint32_t)kb * 32u, ah);
        ldm4(aLo + aRow + (uint32_t)kb * 32u, al);
#pragma unroll
        for (int s = 0; s < NB8 / 2; s++) {
            const int n = n0 + s * 16 + brow;
            const uint32_t c = ((uint32_t)kb << 1) | bsel;
            const uint32_t boff = (uint32_t)n * strideW + ((c ^ (uint32_t)(n & 7)) << 4);
            uint32_t bh[4], bl[4];
            ldm4(wHi + boff, bh);
            ldm4(wLo + boff, bl);
            mma16816(acc[s * 2 + 0], ah, bh[0], bh[2]);
            mma16816(acc[s * 2 + 0], ah, bl[0], bl[2]);
            mma16816(acc[s * 2 + 0], al, bh[0], bh[2]);
            mma16816(acc[s * 2 + 1], ah, bh[1], bh[3]);
            mma16816(acc[s * 2 + 1], ah, bl[1], bl[3]);
            mma16816(acc[s * 2 + 1], al, bh[1], bh[3]);
        }
    }
}

// ---------------- mid-layer epilogue: bias + leaky + split -> smem hi/lo ----------------
template <int NB8>
__device__ __forceinline__ void epi_mid(const float acc[][4], const float* bias,
                                        uint8_t* smem, uint32_t outHi, uint32_t outLo,
                                        uint32_t strideOut, int mt, int n0, int lane)
{
    const int qr = lane >> 2, qc = (lane & 3) * 2;
#pragma unroll
    for (int nf = 0; nf < NB8; nf++) {
        const int col = n0 + nf * 8 + qc;
        const float b0 = bias[col], b1 = bias[col + 1];
#pragma unroll
        for (int hf = 0; hf < 2; hf++) {
            const int row = mt * 16 + qr + hf * 8;
            float f0 = leaky(acc[nf][hf * 2 + 0] + b0);
            float f1 = leaky(acc[nf][hf * 2 + 1] + b1);
            uint32_t hi, lo; split2(f0, f1, hi, lo);
            *(uint32_t*)(smem + outHi + (size_t)row * strideOut + (size_t)col * 2) = hi;
            *(uint32_t*)(smem + outLo + (size_t)row * strideOut + (size_t)col * 2) = lo;
        }
    }
}

// ---------------- final epilogue: bias -> gmem fp32 (+ optional chain into A) ----------
template <int CHAIN>
__device__ __forceinline__ void epi_final(const float acc[][4], const float* bias,
                                          float* __restrict__ gout, uint8_t* smem,
                                          int mt, int n0, int lane)
{
    const int qr = lane >> 2, qc = (lane & 3) * 2;
    float vv[4][4];
#pragma unroll
    for (int nf = 0; nf < 4; nf++) {
        const int col = n0 + nf * 8 + qc;
        const float b0 = bias[col], b1 = bias[col + 1];
#pragma unroll
        for (int hf = 0; hf < 2; hf++) {
            vv[nf][hf * 2 + 0] = acc[nf][hf * 2 + 0] + b0;
            vv[nf][hf * 2 + 1] = acc[nf][hf * 2 + 1] + b1;
            const int row = mt * 16 + qr + hf * 8;
            *(float2*)&gout[(size_t)row * DIM + col] =
                make_float2(vv[nf][hf * 2 + 0], vv[nf][hf * 2 + 1]);
        }
    }
    if (CHAIN) {
        __syncthreads();   // all warps done reading A before overwrite
#pragma unroll
        for (int nf = 0; nf < 4; nf++) {
            const int col = n0 + nf * 8 + qc;
#pragma unroll
            for (int hf = 0; hf < 2; hf++) {
                const int row = mt * 16 + qr + hf * 8;
                uint32_t hi, lo; split2(vv[nf][hf * 2 + 0], vv[nf][hf * 2 + 1], hi, lo);
                *(uint32_t*)(smem + OFF_AH + (size_t)row * STR_A + (size_t)col * 2) = hi;
                *(uint32_t*)(smem + OFF_AL + (size_t)row * STR_A + (size_t)col * 2) = lo;
            }
        }
    }
}

// ---------------- one full 3-layer MLP; weights already resident at OFF_W+wb ----------------
template <int CHAIN>
__device__ __forceinline__ void run_mlp(uint8_t* smem, uint32_t SB, uint32_t wb,
                                        const float* bias, float* __restrict__ gout,
                                        int mt, int nh, int lane)
{
    float acc[4][4];
    mma_layer<8, 2>(SB + OFF_AH, SB + OFF_AL, STR_A,
                    SB + OFF_W + wb + WL1H, SB + OFF_W + wb + WL1L, 256,
                    mt, nh * 16, lane, acc);
    epi_mid<2>(acc, bias, smem, OFF_BH, OFF_BL, STR_B, mt, nh * 16, lane);
    __syncthreads();
    mma_layer<4, 2>(SB + OFF_BH, SB + OFF_BL, STR_B,
                    SB + OFF_W + wb + WL2H, SB + OFF_W + wb + WL2L, 128,
                    mt, nh * 16, lane, acc);
    epi_mid<2>(acc, bias + 64, smem, OFF_AH, OFF_AL, STR_A, mt, nh * 16, lane);
    __syncthreads();
    mma_layer<4, 4>(SB + OFF_AH, SB + OFF_AL, STR_A,
                    SB + OFF_W + wb + WL3H, SB + OFF_W + wb + WL3L, 128,
                    mt, nh * 32, lane, acc);
    epi_final<CHAIN>(acc, bias + 128, gout, smem, mt, nh * 32, lane);
}

// ---------------- persistent kernel: all 8 phases, grid barrier between levels ----------------
__global__ __launch_bounds__(NT, 1)
void persist_kernel(const float* __restrict__ hin, float* __restrict__ h,
                    const int* __restrict__ esrc, const int* __restrict__ emask,
                    const float* ab1, const float* ab2, const float* ab3,
                    const float* ib1, const float* ib2, const float* ib3)
{
    extern __shared__ __align__(16) uint8_t smem[];
    const uint32_t SB = smem_u32(smem);
    const int tid = threadIdx.x, lane = tid & 31, w = tid >> 5;
    const int mt = w & 3, nh = w >> 2;
    float* BIAS = (float*)(smem + OFF_BIAS);
    float* ginv = g_inv;

    // stage ALL weights (once for the whole run) + biases
    {
        const uint4* s4 = (const uint4*)g_wb;
        uint4* d4 = (uint4*)(smem + OFF_W);
        for (int i = tid; i < (2 * WBLOB) / 16; i += NT) d4[i] = s4[i];
    }
    if (tid < 64) {
        BIAS[tid] = ab1[tid];       BIAS[64 + tid] = ab2[tid];
        BIAS[256 + tid] = ib1[tid]; BIAS[320 + tid] = ib2[tid];
    }
    if (tid < 128) { BIAS[128 + tid] = ab3[tid]; BIAS[384 + tid] = ib3[tid]; }
    __syncthreads();

    unsigned bar_target = 0;

    // ---- phase 0: inv-MLP over level-0 input rows ----
    for (int t = blockIdx.x; t < NTILES; t += GRIDSZ) {
        const int nodebase = t * 64;
        const float4* in4 = (const float4*)(hin + (size_t)nodebase * DIM);
        for (int i = tid; i < 64 * 32; i += NT) {
            const int row = i >> 5, c4 = i & 31;
            float4 x = in4[(size_t)row * 32 + c4];
            uint32_t h0, l0, h1, l1;
            split2(x.x, x.y, h0, l0);
            split2(x.z, x.w, h1, l1);
            const size_t off = (size_t)row * STR_A + (size_t)c4 * 8;
            *(uint32_t*)(smem + OFF_AH + off) = h0;
            *(uint32_t*)(smem + OFF_AH + off + 4) = h1;
            *(uint32_t*)(smem + OFF_AL + off) = l0;
            *(uint32_t*)(smem + OFF_AL + off + 4) = l1;
        }
        __syncthreads();
        run_mlp<0>(smem, SB, WBLOB, BIAS + 256, ginv + (size_t)nodebase * DIM, mt, nh, lane);
        __syncthreads();
    }
    bar_target += GRIDSZ;
    grid_barrier(bar_target);

    // ---- levels 0..6 ----
    for (int lvl = 0; lvl < 7; lvl++) {
        const int* src = esrc  + (size_t)lvl * NPL * DEG;
        const int* msk = emask + (size_t)lvl * NPL * DEG;
        const bool do_inv = (lvl < 6);
        for (int t = blockIdx.x; t < NTILES; t += GRIDSZ) {
            const int nodebase = t * 64;
            // stage indices (aliases B buffers — free here)
            ((int4*)(smem + OFF_IDX))[tid] = (tid < 256)
                ? ((const int4*)(src + (size_t)nodebase * DEG))[tid]
                : ((const int4*)(msk + (size_t)nodebase * DEG))[tid - 256];
            __syncthreads();
            // gather + masked mean -> A (hi/lo)
            {
                const int* sidx = (const int*)(smem + OFF_IDX);
                const int* midx = sidx + 1024;
                for (int rr = 0; rr < 4; rr += 2) {
                    const int r0 = w * 4 + rr, r1 = r0 + 1;
                    float4 a0 = make_float4(0.f, 0.f, 0.f, 0.f);
                    float4 a1 = make_float4(0.f, 0.f, 0.f, 0.f);
#pragma unroll 8
                    for (int e = 0; e < DEG; e++) {
                        const int s0 = sidx[r0 * DEG + e], m0 = midx[r0 * DEG + e];
                        const int s1 = sidx[r1 * DEG + e], m1 = midx[r1 * DEG + e];
                        const float4* p0 = (const float4*)((m0 ? ginv : h) + (size_t)s0 * DIM);
                        const float4* p1 = (const float4*)((m1 ? ginv : h) + (size_t)s1 * DIM);
                        float4 v0 = p0[lane], v1 = p1[lane];
                        a0.x += v0.x; a0.y += v0.y; a0.z += v0.z; a0.w += v0.w;
                        a1.x += v1.x; a1.y += v1.y; a1.z += v1.z; a1.w += v1.w;
                    }
                    const float s16 = 0.0625f;
                    uint32_t h0, l0, h1, l1;
                    split2(a0.x * s16, a0.y * s16, h0, l0);
                    split2(a0.z * s16, a0.w * s16, h1, l1);
                    size_t off = (size_t)r0 * STR_A + (size_t)lane * 8;
                    *(uint32_t*)(smem + OFF_AH + off) = h0;
                    *(uint32_t*)(smem + OFF_AH + off + 4) = h1;
                    *(uint32_t*)(smem + OFF_AL + off) = l0;
                    *(uint32_t*)(smem + OFF_AL + off + 4) = l1;
                    split2(a1.x * s16, a1.y * s16, h0, l0);
                    split2(a1.z * s16, a1.w * s16, h1, l1);
                    off = (size_t)r1 * STR_A + (size_t)lane * 8;
                    *(uint32_t*)(smem + OFF_AH + off) = h0;
                    *(uint32_t*)(smem + OFF_AH + off + 4) = h1;
                    *(uint32_t*)(smem + OFF_AL + off) = l0;
                    *(uint32_t*)(smem + OFF_AL + off + 4) = l1;
                }
            }
            __syncthreads();

            float* gout = h + ((size_t)(lvl + 1) * NPL + (size_t)nodebase) * DIM;
            if (do_inv) {
                run_mlp<1>(smem, SB, 0, BIAS, gout, mt, nh, lane);
                __syncthreads();   // A now holds and-output (all warps wrote it)
                float* gi = ginv + ((size_t)(lvl + 1) * NPL + (size_t)nodebase) * DIM;
                run_mlp<0>(smem, SB, WBLOB, BIAS + 256, gi, mt, nh, lane);
            } else {
                run_mlp<0>(smem, SB, 0, BIAS, gout, mt, nh, lane);
            }
            __syncthreads();   // tile end: A/B free for next tile
        }
        bar_target += GRIDSZ;
        if (lvl < 6) grid_barrier(bar_target);
    }
}

// ---------------------------------------------------------------------------
extern "C" void kernel_launch(void* const* d_in, const int* in_sizes, int n_in,
                              void* d_out, int out_size)
{
    (void)in_sizes; (void)n_in; (void)out_size;
    const float* h_in  = (const float*)d_in[0];
    const int*   esrc  = (const int*)d_in[1];
    const int*   emask = (const int*)d_in[2];
    const float* iw1 = (const float*)d_in[3];
    const float* ib1 = (const float*)d_in[4];
    const float* iw2 = (const float*)d_in[5];
    const float* ib2 = (const float*)d_in[6];
    const float* iw3 = (const float*)d_in[7];
    const float* ib3 = (const float*)d_in[8];
    const float* aw1 = (const float*)d_in[9];
    const float* ab1 = (const float*)d_in[10];
    const float* aw2 = (const float*)d_in[11];
    const float* ab2 = (const float*)d_in[12];
    const float* aw3 = (const float*)d_in[13];
    const float* ab3 = (const float*)d_in[14];

    float* h = (float*)d_out;

    static bool once = false;
    if (!once) {
        cudaFuncSetAttribute(persist_kernel, cudaFuncAttributeMaxDynamicSharedMemorySize, SM_TOTAL);
        once = true;
    }

    // level-0 rows of the output are the input rows
    cudaMemcpyAsync(h, h_in, (size_t)NPL * DIM * sizeof(float), cudaMemcpyDeviceToDevice, 0);

    // converts weights AND resets g_bar (deterministic per launch / graph replay)
    prep_weights<<<6, 256>>>(aw1, aw2, aw3, iw1, iw2, iw3);

    persist_kernel<<<GRIDSZ, NT, SM_TOTAL>>>(h_in, h, esrc, emask,
                                             ab1, ab2, ab3, ib1, ib2, ib3);
}